// round 8
// baseline (speedup 1.0000x reference)
#include <cuda_runtime.h>
#include <cstdint>

#define B_   32
#define L_   256
#define T_   1600
#define C_   40
#define PADM 1.0e12f

// ---------------- scratch (__device__ globals; no allocation allowed) ----------------
__device__ __align__(16) float g_coefA[B_ * C_ * 2 * L_];   // invvar, duplicated pairs
__device__ __align__(16) float g_coefB[B_ * C_ * 2 * L_];   // mu*invvar, duplicated pairs
__device__ __align__(16) float g_t3 [B_ * L_];
__device__ __align__(16) float g_mlv[B_ * L_];

// ---------------- packed f32x2 helpers (sm_103a) ----------------
__device__ __forceinline__ unsigned long long pack2(float lo, float hi) {
    unsigned long long r;
    asm("mov.b64 %0, {%1,%2};" : "=l"(r) : "f"(lo), "f"(hi));
    return r;
}
#define FFMA2_ACC(d, a, b) \
    asm("fma.rn.f32x2 %0, %1, %2, %0;" : "+l"(d) : "l"(a), "l"(b))
#define FFMA2(d, a, b, c) \
    asm("fma.rn.f32x2 %0, %1, %2, %3;" : "=l"(d) : "l"(a), "l"(b), "l"(c))
#define ADD2(d, a, b) \
    asm("add.rn.f32x2 %0, %1, %2;" : "=l"(d) : "l"(a), "l"(b))

// volatile 128-bit shared ld/st (single-instruction mailbox access)
__device__ __forceinline__ uint4 ldsv4v(unsigned a) {
    uint4 r;
    asm volatile("ld.volatile.shared.v4.b32 {%0,%1,%2,%3},[%4];"
                 : "=r"(r.x), "=r"(r.y), "=r"(r.z), "=r"(r.w) : "r"(a));
    return r;
}
__device__ __forceinline__ void stsv4v(unsigned a, uint4 v) {
    asm volatile("st.volatile.shared.v4.b32 [%0],{%1,%2,%3,%4};"
                 :: "r"(a), "r"(v.x), "r"(v.y), "r"(v.z), "r"(v.w));
}

// ---------------- K0: per-(b,l) coefficients ----------------
__global__ void k0_coef(const float* __restrict__ mu_logvar) {
    int idx = blockIdx.x * 128 + threadIdx.x;          // 0 .. B*L-1
    int b = idx >> 8;
    int l = idx & (L_ - 1);
    const float* row = mu_logvar + (size_t)idx * (2 * C_);
    float* A  = g_coefA + (size_t)b * C_ * 2 * L_ + 2 * l;
    float* Bc = g_coefB + (size_t)b * C_ * 2 * L_ + 2 * l;
    float t3 = 0.f, slv = 0.f;
    for (int c = 0; c < C_; c++) {
        float mu = row[c];
        float lv = row[C_ + c];
        float iv = expf(-lv);
        float miv = mu * iv;
        A [c * 2 * L_]     = iv;
        A [c * 2 * L_ + 1] = iv;
        Bc[c * 2 * L_]     = miv;
        Bc[c * 2 * L_ + 1] = miv;
        t3 = fmaf(mu, miv, t3);
        slv += lv;
    }
    g_t3 [idx] = t3;
    g_mlv[idx] = slv * (1.0f / C_);
}

// ---------------- Kz: zero the alignment output region ----------------
__global__ void kz_zero(float4* __restrict__ p, int n4) {
    int i = blockIdx.x * blockDim.x + threadIdx.x;
    int stride = gridDim.x * blockDim.x;
    float4 z = make_float4(0.f, 0.f, 0.f, 0.f);
    for (; i < n4; i += stride) p[i] = z;
}

// ---------------- K1: lp[b][l][t] via packed FFMA2 GEMM ----------------
__global__ __launch_bounds__(256) void k1_lp(const float* __restrict__ z,
                                             float* __restrict__ lp_out) {
    __shared__ __align__(16) float zs [C_][64];
    __shared__ __align__(16) float z2s[C_][64];
    int b  = blockIdx.z;
    int l0 = blockIdx.y * 128;
    int t0 = blockIdx.x * 64;
    int tid = threadIdx.x;

    const float* zb = z + (size_t)b * C_ * T_ + t0;
    for (int i = tid; i < C_ * 64; i += 256) {
        int c = i >> 6, j = i & 63;
        float v = zb[(size_t)c * T_ + j];
        zs [c][j] = v;
        z2s[c][j] = v * v;
    }
    __syncthreads();

    int lg = tid >> 3, tg = tid & 7;
    int lbase = l0 + lg * 4;

    unsigned long long s1[4][4], s2[4][4];
#pragma unroll
    for (int r = 0; r < 4; r++)
#pragma unroll
        for (int j = 0; j < 4; j++) { s1[r][j] = 0ull; s2[r][j] = 0ull; }

    const float* cA = g_coefA + (size_t)b * C_ * 2 * L_ + 2 * lbase;
    const float* cB = g_coefB + (size_t)b * C_ * 2 * L_ + 2 * lbase;

#pragma unroll 2
    for (int c = 0; c < C_; c++) {
        ulonglong2 aL = *(const ulonglong2*)(cA + (size_t)c * 2 * L_);
        ulonglong2 aH = *(const ulonglong2*)(cA + (size_t)c * 2 * L_ + 4);
        ulonglong2 bL = *(const ulonglong2*)(cB + (size_t)c * 2 * L_);
        ulonglong2 bH = *(const ulonglong2*)(cB + (size_t)c * 2 * L_ + 4);
        unsigned long long ar[4] = {aL.x, aL.y, aH.x, aH.y};
        unsigned long long br[4] = {bL.x, bL.y, bH.x, bH.y};
        ulonglong2 q0 = *(const ulonglong2*)&z2s[c][tg * 8];
        ulonglong2 q1 = *(const ulonglong2*)&z2s[c][tg * 8 + 4];
        ulonglong2 w0 = *(const ulonglong2*)&zs [c][tg * 8];
        ulonglong2 w1 = *(const ulonglong2*)&zs [c][tg * 8 + 4];
        unsigned long long z2p[4] = {q0.x, q0.y, q1.x, q1.y};
        unsigned long long zp [4] = {w0.x, w0.y, w1.x, w1.y};
#pragma unroll
        for (int r = 0; r < 4; r++) {
#pragma unroll
            for (int j = 0; j < 4; j++) {
                FFMA2_ACC(s1[r][j], ar[r], z2p[j]);
                FFMA2_ACC(s2[r][j], br[r], zp[j]);
            }
        }
    }

    float4 t34 = *(const float4*)(g_t3  + b * L_ + lbase);
    float4 mv4 = *(const float4*)(g_mlv + b * L_ + lbase);
    float t3a[4] = {t34.x, t34.y, t34.z, t34.w};
    float mva[4] = {mv4.x, mv4.y, mv4.z, mv4.w};
    unsigned long long m2 = pack2(-2.0f, -2.0f);
    unsigned long long c1 = pack2(-0.0125f, -0.0125f);   // -0.5/C
#pragma unroll
    for (int r = 0; r < 4; r++) {
        unsigned long long tp = pack2(t3a[r], t3a[r]);
        unsigned long long dp = pack2(-0.5f * mva[r], -0.5f * mva[r]);
        unsigned long long o[4];
#pragma unroll
        for (int j = 0; j < 4; j++) {
            unsigned long long mse;
            FFMA2(mse, s2[r][j], m2, s1[r][j]);   // s1 - 2*s2
            ADD2(mse, mse, tp);                   // + t3
            FFMA2(o[j], mse, c1, dp);             // *(-1/80) + (-0.5*mlv)
        }
        float* orow = lp_out + ((size_t)b * L_ + lbase + r) * T_ + t0 + tg * 8;
        ((ulonglong2*)orow)[0] = make_ulonglong2(o[0], o[1]);
        ((ulonglong2*)orow)[1] = make_ulonglong2(o[2], o[3]);
    }
}

// ---------------- K2: 2-warp DP, 4 text-positions per lane, no ring ----------------
// smem layout (bytes):
//   [0, 51200)       D32 nibble words [200 groups][64 q]   (q = l>>2, 8 cols/word)
//   [51200, 76800)   mailbox: 1600 slots x 16B {tag=t+1, a127, b127, pad}
//   [76800, 83200)   b0h[T]    beta[l=0] history
//   [83200, 89600)   b255h[T]  beta[l=255] history
//   [89600, 96000)   path[T]
#define SMB_MB    51200
#define SMB_B0H   76800
#define SMB_B255H 83200
#define SMB_PATH  89600
#define SMB_TOT   96000

#define COMP4(v, j) ((j) == 0 ? (v).x : (j) == 1 ? (v).y : (j) == 2 ? (v).z : (v).w)

__device__ __forceinline__ float lae(float aold, float am, float lpe) {
    float d = aold - am;
    float m = fmaxf(aold, am);
    return m + __logf(1.0f + __expf(-fabsf(d))) + lpe;
}

__global__ __launch_bounds__(64, 1) void k2_dp(const float* __restrict__ lp,
                                               const int* __restrict__ tlen,
                                               const int* __restrict__ mlen,
                                               float* __restrict__ out_loss,
                                               float* __restrict__ out_align) {
    extern __shared__ unsigned char smraw[];
    unsigned* D32 = (unsigned*)smraw;
    float* b0h    = (float*)(smraw + SMB_B0H);
    float* b255h  = (float*)(smraw + SMB_B255H);
    int*   path   = (int*)(smraw + SMB_PATH);
    unsigned smbase = (unsigned)__cvta_generic_to_shared(smraw);
    unsigned mb     = smbase + SMB_MB;

    int b   = blockIdx.x;
    int tid = threadIdx.x;
    int w   = tid >> 5, lane = tid & 31;
    int ml = mlen[b], tl = tlen[b];
    int mlm1 = ml - 1, tlm1 = tl - 1;
    int losstid = tlm1 >> 2, lossslot = tlm1 & 3;

    const float* p0 = lp + ((size_t)b * L_ + tid * 4) * T_;

    // zero mailbox tags
    {
        uint4* m4 = (uint4*)(smraw + SMB_MB);
        uint4 zz = make_uint4(0u, 0u, 0u, 0u);
        for (int i = tid; i < T_; i += 64) m4[i] = zz;
    }

    // init t=0: alpha/beta = lp[b,0,0] at l==0 else -PADM
    float A0, A1, A2, A3, Bv0, Bv1, Bv2, Bv3;
    {
        float v0 = (tid == 0) ? __ldg(p0) : -PADM;
        A0 = v0; A1 = -PADM; A2 = -PADM; A3 = -PADM;
        Bv0 = v0; Bv1 = -PADM; Bv2 = -PADM; Bv3 = -PADM;
        if (tid == 0)  b0h[0]   = Bv0;
        if (tid == 63) b255h[0] = Bv3;
        if (tid == 31)
            stsv4v(mb, make_uint4(1u, __float_as_uint(-PADM), __float_as_uint(-PADM), 0u));
    }
    // prefetch t=0..3 for my 4 rows
    float4 c0 = *(const float4*)(p0);
    float4 c1 = *(const float4*)(p0 + T_);
    float4 c2 = *(const float4*)(p0 + 2 * T_);
    float4 c3 = *(const float4*)(p0 + 3 * T_);
    __syncthreads();

    unsigned acc = 0;

    for (int k = 0; k < T_ / 4; k++) {
        float4 n0, n1, n2, n3;
        if (k + 1 < T_ / 4) {
            n0 = *(const float4*)(p0 + 4 * (k + 1));
            n1 = *(const float4*)(p0 + T_ + 4 * (k + 1));
            n2 = *(const float4*)(p0 + 2 * T_ + 4 * (k + 1));
            n3 = *(const float4*)(p0 + 3 * T_ + 4 * (k + 1));
        } else { n0 = n1 = n2 = n3 = make_float4(0.f, 0.f, 0.f, 0.f); }

#pragma unroll
        for (int j = 0; j < 4; j++) {
            int t = 4 * k + j;
            if (k == 0 && j == 0) continue;
            // boundary at t-1
            float pa = __shfl_up_sync(0xffffffffu, A3, 1);
            float pb = __shfl_up_sync(0xffffffffu, Bv3, 1);
            if (w) {
                unsigned saddr = mb + (unsigned)(t - 1) * 16u;
                uint4 s = ldsv4v(saddr);
                while (s.x != (unsigned)t) s = ldsv4v(saddr);
                if (lane == 0) { pa = __uint_as_float(s.y); pb = __uint_as_float(s.z); }
            } else if (lane == 0) { pa = -PADM; pb = -PADM; }
            // decision nibble for column t-1 (from OLD beta); l=0 bit fixed up later
            unsigned nib = (unsigned)(pb > Bv0)
                         | ((unsigned)(Bv0 > Bv1) << 1)
                         | ((unsigned)(Bv1 > Bv2) << 2)
                         | ((unsigned)(Bv2 > Bv3) << 3);
            acc |= nib << (4 * ((t - 1) & 7));
            if (((t - 1) & 7) == 7) { D32[((t - 1) >> 3) * 64 + tid] = acc; acc = 0; }
            // lp values
            float l0 = COMP4(c0, j), l1 = COMP4(c1, j);
            float l2 = COMP4(c2, j), l3 = COMP4(c3, j);
            // alpha (logaddexp) — all 4 read OLD values: ILP-4
            float na0 = lae(A0, pa, l0 + 1e-7f);
            float na1 = lae(A1, A0, l1 + 1e-7f);
            float na2 = lae(A2, A1, l2 + 1e-7f);
            float na3 = lae(A3, A2, l3 + 1e-7f);
            // beta (viterbi)
            float nb0 = fmaxf(Bv0, pb)  + l0;
            float nb1 = fmaxf(Bv1, Bv0) + l1;
            float nb2 = fmaxf(Bv2, Bv1) + l2;
            float nb3 = fmaxf(Bv3, Bv2) + l3;
            if (t == mlm1 && tid == losstid) {
                float v = (lossslot == 0) ? na0 : (lossslot == 1) ? na1
                        : (lossslot == 2) ? na2 : na3;
                out_loss[b] = -v / (float)ml;
            }
            if (tid == 31)
                stsv4v(mb + (unsigned)t * 16u,
                       make_uint4((unsigned)(t + 1), __float_as_uint(na3),
                                  __float_as_uint(nb3), 0u));
            if (tid == 0)  b0h[t]   = nb0;
            if (tid == 63) b255h[t] = nb3;
            A0 = na0; A1 = na1; A2 = na2; A3 = na3;
            Bv0 = nb0; Bv1 = nb1; Bv2 = nb2; Bv3 = nb3;
        }
        c0 = n0; c1 = n1; c2 = n2; c3 = n3;
    }

    // column T-1 decision bits (from final beta values)
    {
        float pb = __shfl_up_sync(0xffffffffu, Bv3, 1);
        if (w) {
            unsigned saddr = mb + (unsigned)(T_ - 1) * 16u;
            uint4 s = ldsv4v(saddr);
            while (s.x != (unsigned)T_) s = ldsv4v(saddr);
            if (lane == 0) pb = __uint_as_float(s.z);
        } else if (lane == 0) pb = -PADM;
        unsigned nib = (unsigned)(pb > Bv0)
                     | ((unsigned)(Bv0 > Bv1) << 1)
                     | ((unsigned)(Bv1 > Bv2) << 2)
                     | ((unsigned)(Bv2 > Bv3) << 3);
        acc |= nib << 28;                       // (T-1)&7 == 7
        D32[((T_ - 1) >> 3) * 64 + tid] = acc;
    }
    __syncthreads();

    // fix up bit for l=0 (wrap: beta[255] > beta[0]) — one thread owns a whole word
    for (int g = tid; g < 200; g += 64) {
        unsigned wv = D32[g * 64];
        #pragma unroll
        for (int c8 = 0; c8 < 8; c8++) {
            int c = g * 8 + c8;
            unsigned bit = (b255h[c] > b0h[c]) ? 1u : 0u;
            wv = (wv & ~(1u << (4 * c8))) | (bit << (4 * c8));
        }
        D32[g * 64] = wv;
    }
    __syncthreads();

    // serial backtrack: nibble layout word = D32[(col>>3)*64 + (r>>2)],
    // bit = 4*(col&7) + (r&3)
    if (tid == 0) {
        int r = tlm1;
        path[0] = r;
        int k = 1, col = mlm1 - 1;
        // singles until col ≡ 7 (mod 8)
        while (k <= mlm1 && (col & 7) != 7) {
            int br = r & 255;
            unsigned word = D32[(col >> 3) * 64 + (br >> 2)];
            int bit = (word >> (4 * (col & 7) + (br & 3))) & 1;
            int tmp = r - bit + 1;
            r = (tmp > 0 ? tmp : 0) - 1;
            path[k++] = r; col--;
        }
        // aligned batches of 8 columns (same group word per q)
        while (k + 7 <= mlm1) {
            int g = col >> 3;
            int q0 = (r & 255) >> 2;
            unsigned W0 = D32[g * 64 + q0];
            unsigned W1 = D32[g * 64 + (q0 > 0 ? q0 - 1 : 0)];
            unsigned W2 = D32[g * 64 + (q0 > 1 ? q0 - 2 : 0)];
            #pragma unroll
            for (int d = 0; d < 8; d++) {
                int br = r & 255;
                int q = br >> 2;
                unsigned word = (q == q0) ? W0 : (q == q0 - 1) ? W1 : W2;
                int bit = (word >> (4 * (col & 7) + (br & 3))) & 1;
                int tmp = r - bit + 1;
                r = (tmp > 0 ? tmp : 0) - 1;
                path[k++] = r; col--;
            }
        }
        while (k <= mlm1) {
            int br = r & 255;
            unsigned word = D32[(col >> 3) * 64 + (br >> 2)];
            int bit = (word >> (4 * (col & 7) + (br & 3))) & 1;
            int tmp = r - bit + 1;
            r = (tmp > 0 ? tmp : 0) - 1;
            path[k++] = r; col--;
        }
    }
    __syncthreads();

    // write one-hot ones: final[t] = onehot(path[ml-1-t]) for t < ml
    size_t abase = (size_t)b * T_ * L_;
    for (int t = tid; t < ml; t += 64) {
        int r = path[mlm1 - t];
        if (r >= 0) out_align[abase + (size_t)t * L_ + r] = 1.0f;
    }
}

// ---------------- launch ----------------
extern "C" void kernel_launch(void* const* d_in, const int* in_sizes, int n_in,
                              void* d_out, int out_size) {
    const float* mu_logvar = (const float*)d_in[0];   // [B, L, 2C]
    const float* z         = (const float*)d_in[1];   // [B, C, T]
    const int*   tlen      = (const int*)d_in[2];     // [B]
    const int*   mlen      = (const int*)d_in[3];     // [B]

    float* out       = (float*)d_out;
    float* out_loss  = out;                                   // [B]
    float* out_align = out + B_;                              // [B, T, L]
    float* out_lp    = out_align + (size_t)B_ * T_ * L_;      // [B, L, T]

    cudaFuncSetAttribute(k2_dp, cudaFuncAttributeMaxDynamicSharedMemorySize,
                         SMB_TOT);

    kz_zero<<<2048, 256>>>((float4*)out_align, (B_ * T_ * L_) / 4);
    k0_coef<<<(B_ * L_) / 128, 128>>>(mu_logvar);
    dim3 g1(T_ / 64, L_ / 128, B_);
    k1_lp<<<g1, 256>>>(z, out_lp);
    k2_dp<<<B_, 64, SMB_TOT>>>(out_lp, tlen, mlen, out_loss, out_align);
}

// round 9
// speedup vs baseline: 1.7540x; 1.7540x over previous
#include <cuda_runtime.h>
#include <cstdint>

#define B_   32
#define L_   256
#define T_   1600
#define C_   40
#define PADM 1.0e12f

// ---------------- scratch (__device__ globals; no allocation allowed) ----------------
__device__ __align__(16) float g_coefA[B_ * C_ * 2 * L_];   // invvar, duplicated pairs
__device__ __align__(16) float g_coefB[B_ * C_ * 2 * L_];   // mu*invvar, duplicated pairs
__device__ __align__(16) float g_t3 [B_ * L_];
__device__ __align__(16) float g_mlv[B_ * L_];

// ---------------- packed f32x2 helpers (sm_103a) ----------------
__device__ __forceinline__ unsigned long long pack2(float lo, float hi) {
    unsigned long long r;
    asm("mov.b64 %0, {%1,%2};" : "=l"(r) : "f"(lo), "f"(hi));
    return r;
}
#define FFMA2_ACC(d, a, b) \
    asm("fma.rn.f32x2 %0, %1, %2, %0;" : "+l"(d) : "l"(a), "l"(b))
#define FFMA2(d, a, b, c) \
    asm("fma.rn.f32x2 %0, %1, %2, %3;" : "=l"(d) : "l"(a), "l"(b), "l"(c))
#define ADD2(d, a, b) \
    asm("add.rn.f32x2 %0, %1, %2;" : "=l"(d) : "l"(a), "l"(b))

// volatile shared accessors
__device__ __forceinline__ uint2 ldsv2v(unsigned a) {
    uint2 r;
    asm volatile("ld.volatile.shared.v2.b32 {%0,%1},[%2];"
                 : "=r"(r.x), "=r"(r.y) : "r"(a));
    return r;
}
__device__ __forceinline__ void stsv2v(unsigned a, float x, float y) {
    asm volatile("st.volatile.shared.v2.b32 [%0],{%1,%2};"
                 :: "r"(a), "r"(__float_as_uint(x)), "r"(__float_as_uint(y)));
}
__device__ __forceinline__ int ldsv1v(unsigned a) {
    int r;
    asm volatile("ld.volatile.shared.b32 %0,[%1];" : "=r"(r) : "r"(a));
    return r;
}
__device__ __forceinline__ void stsv1v(unsigned a, int v) {
    asm volatile("st.volatile.shared.b32 [%0],%1;" :: "r"(a), "r"(v));
}

// ---------------- K0: per-(b,l) coefficients ----------------
__global__ void k0_coef(const float* __restrict__ mu_logvar) {
    int idx = blockIdx.x * 128 + threadIdx.x;          // 0 .. B*L-1
    int b = idx >> 8;
    int l = idx & (L_ - 1);
    const float* row = mu_logvar + (size_t)idx * (2 * C_);
    float* A  = g_coefA + (size_t)b * C_ * 2 * L_ + 2 * l;
    float* Bc = g_coefB + (size_t)b * C_ * 2 * L_ + 2 * l;
    float t3 = 0.f, slv = 0.f;
    for (int c = 0; c < C_; c++) {
        float mu = row[c];
        float lv = row[C_ + c];
        float iv = expf(-lv);
        float miv = mu * iv;
        A [c * 2 * L_]     = iv;
        A [c * 2 * L_ + 1] = iv;
        Bc[c * 2 * L_]     = miv;
        Bc[c * 2 * L_ + 1] = miv;
        t3 = fmaf(mu, miv, t3);
        slv += lv;
    }
    g_t3 [idx] = t3;
    g_mlv[idx] = slv * (1.0f / C_);
}

// ---------------- Kz: zero the alignment output region ----------------
__global__ void kz_zero(float4* __restrict__ p, int n4) {
    int i = blockIdx.x * blockDim.x + threadIdx.x;
    int stride = gridDim.x * blockDim.x;
    float4 z = make_float4(0.f, 0.f, 0.f, 0.f);
    for (; i < n4; i += stride) p[i] = z;
}

// ---------------- K1: lp[b][l][t] via packed FFMA2 GEMM ----------------
__global__ __launch_bounds__(256) void k1_lp(const float* __restrict__ z,
                                             float* __restrict__ lp_out) {
    __shared__ __align__(16) float zs [C_][64];
    __shared__ __align__(16) float z2s[C_][64];
    int b  = blockIdx.z;
    int l0 = blockIdx.y * 128;
    int t0 = blockIdx.x * 64;
    int tid = threadIdx.x;

    const float* zb = z + (size_t)b * C_ * T_ + t0;
    for (int i = tid; i < C_ * 64; i += 256) {
        int c = i >> 6, j = i & 63;
        float v = zb[(size_t)c * T_ + j];
        zs [c][j] = v;
        z2s[c][j] = v * v;
    }
    __syncthreads();

    int lg = tid >> 3, tg = tid & 7;
    int lbase = l0 + lg * 4;

    unsigned long long s1[4][4], s2[4][4];
#pragma unroll
    for (int r = 0; r < 4; r++)
#pragma unroll
        for (int j = 0; j < 4; j++) { s1[r][j] = 0ull; s2[r][j] = 0ull; }

    const float* cA = g_coefA + (size_t)b * C_ * 2 * L_ + 2 * lbase;
    const float* cB = g_coefB + (size_t)b * C_ * 2 * L_ + 2 * lbase;

#pragma unroll 2
    for (int c = 0; c < C_; c++) {
        ulonglong2 aL = *(const ulonglong2*)(cA + (size_t)c * 2 * L_);
        ulonglong2 aH = *(const ulonglong2*)(cA + (size_t)c * 2 * L_ + 4);
        ulonglong2 bL = *(const ulonglong2*)(cB + (size_t)c * 2 * L_);
        ulonglong2 bH = *(const ulonglong2*)(cB + (size_t)c * 2 * L_ + 4);
        unsigned long long ar[4] = {aL.x, aL.y, aH.x, aH.y};
        unsigned long long br[4] = {bL.x, bL.y, bH.x, bH.y};
        ulonglong2 q0 = *(const ulonglong2*)&z2s[c][tg * 8];
        ulonglong2 q1 = *(const ulonglong2*)&z2s[c][tg * 8 + 4];
        ulonglong2 w0 = *(const ulonglong2*)&zs [c][tg * 8];
        ulonglong2 w1 = *(const ulonglong2*)&zs [c][tg * 8 + 4];
        unsigned long long z2p[4] = {q0.x, q0.y, q1.x, q1.y};
        unsigned long long zp [4] = {w0.x, w0.y, w1.x, w1.y};
#pragma unroll
        for (int r = 0; r < 4; r++) {
#pragma unroll
            for (int j = 0; j < 4; j++) {
                FFMA2_ACC(s1[r][j], ar[r], z2p[j]);
                FFMA2_ACC(s2[r][j], br[r], zp[j]);
            }
        }
    }

    float4 t34 = *(const float4*)(g_t3  + b * L_ + lbase);
    float4 mv4 = *(const float4*)(g_mlv + b * L_ + lbase);
    float t3a[4] = {t34.x, t34.y, t34.z, t34.w};
    float mva[4] = {mv4.x, mv4.y, mv4.z, mv4.w};
    unsigned long long m2 = pack2(-2.0f, -2.0f);
    unsigned long long c1 = pack2(-0.0125f, -0.0125f);   // -0.5/C
#pragma unroll
    for (int r = 0; r < 4; r++) {
        unsigned long long tp = pack2(t3a[r], t3a[r]);
        unsigned long long dp = pack2(-0.5f * mva[r], -0.5f * mva[r]);
        unsigned long long o[4];
#pragma unroll
        for (int j = 0; j < 4; j++) {
            unsigned long long mse;
            FFMA2(mse, s2[r][j], m2, s1[r][j]);   // s1 - 2*s2
            ADD2(mse, mse, tp);                   // + t3
            FFMA2(o[j], mse, c1, dp);             // *(-1/80) + (-0.5*mlv)
        }
        float* orow = lp_out + ((size_t)b * L_ + lbase + r) * T_ + t0 + tg * 8;
        ((ulonglong2*)orow)[0] = make_ulonglong2(o[0], o[1]);
        ((ulonglong2*)orow)[1] = make_ulonglong2(o[2], o[3]);
    }
}

// ---------------- K2: 8-warp DP, feed-forward mailbox (no ring) ----------------
// smem layout (bytes):
//   [0, 51200)         D ballot words [T_][8]
//   [51200, 153600)    mailbox: 8 warps x 1600 slots x 8B {an, bn}
//   [153600, 160000)   b0h[T_]  (beta[l=0] history, for wrap-bit fixup)
//   [160000, 166400)   path[T_]
//   [166400, 166432)   prog[8]  (highest t published per warp)
#define SMB_MB    51200
#define SMB_B0H   153600
#define SMB_PATH  160000
#define SMB_PROG  166400
#define SMB_TOT   166448

__global__ __launch_bounds__(256, 1) void k2_dp(const float* __restrict__ lp,
                                                const int* __restrict__ tlen,
                                                const int* __restrict__ mlen,
                                                float* __restrict__ out_loss,
                                                float* __restrict__ out_align) {
    extern __shared__ unsigned char smraw[];
    unsigned* D  = (unsigned*)smraw;
    float* b0h   = (float*)(smraw + SMB_B0H);
    int*   path  = (int*)(smraw + SMB_PATH);
    unsigned smbase = (unsigned)__cvta_generic_to_shared(smraw);
    unsigned mb     = smbase + SMB_MB;
    unsigned progb  = smbase + SMB_PROG;

    int b = blockIdx.x;
    int l = threadIdx.x;
    int w = l >> 5, lane = l & 31;
    int ml = mlen[b], tl = tlen[b];
    int mlm1 = ml - 1, tlm1 = tl - 1;
    const float* p = lp + ((size_t)b * L_ + l) * T_;

    unsigned mb_self = mb + (unsigned)w * 12800u;              // this warp's slots
    unsigned mb_src  = mb + (unsigned)(w - 1) * 12800u;        // predecessor (w>=1)
    unsigned prog_self = progb + (unsigned)w * 4u;
    unsigned prog_src  = progb + (unsigned)(w - 1) * 4u;

    if (l < 8) stsv1v(progb + (unsigned)l * 4u, 0);            // prog init

    float4 vcur = *(const float4*)p;           // lp[t=0..3]
    float a  = (l == 0) ? vcur.x : -PADM;      // alpha(t=0)
    float bt = a;                              // beta(t=0)

    if (lane == 31) stsv2v(mb_self, -PADM, -PADM);   // slot t=0
    if (l == 0)     b0h[0] = bt;
    __syncthreads();   // prog + slot0 visible

    float4 vnext = *(const float4*)(p + 4);
    int pc = 0;        // cached predecessor progress (lane0 of warps 1..7)

    for (int k = 0; k < T_ / 4; k++) {
        float4 vpref = vcur;
        if (k + 2 < T_ / 4) vpref = *(const float4*)(p + 4 * (k + 2));
        float lt[4] = {vcur.x, vcur.y, vcur.z, vcur.w};
#pragma unroll
        for (int j = 0; j < 4; j++) {
            int t = 4 * k + j;
            if (t == 0) continue;
            float sa = __shfl_up_sync(0xffffffffu, a, 1);
            float sb = __shfl_up_sync(0xffffffffu, bt, 1);
            float am, bm, bw;
            if (lane == 0) {
                if (w) {
                    if (pc < t - 1) {
                        do { pc = ldsv1v(prog_src); } while (pc < t - 1);
                    }
                    uint2 s = ldsv2v(mb_src + (unsigned)(t - 1) * 8u);
                    am = __uint_as_float(s.x);
                    bm = __uint_as_float(s.y);
                    bw = bm;
                } else { am = -PADM; bm = -PADM; bw = -PADM; } // wrap bit fixed later
            } else { am = sa; bm = sb; bw = sb; }
            // decision bits for column t-1 (beta values at t-1)
            unsigned bal = __ballot_sync(0xffffffffu, bw > bt);
            if (lane == 0) D[(t - 1) * 8 + w] = bal;
            // recurrences
            float lpv = lt[j];
            float d  = a - am;
            float m  = fmaxf(a, am);
            float an = m + __logf(1.0f + __expf(-fabsf(d))) + (lpv + 1e-7f);
            float bn = fmaxf(bt, bm) + lpv;
            if (t == mlm1 && l == tlm1) out_loss[b] = -an / (float)ml;
            if (lane == 31) {
                stsv2v(mb_self + (unsigned)t * 8u, an, bn);
                stsv1v(prog_self, t);
            }
            if (l == 0) b0h[t] = bn;
            a = an; bt = bn;
        }
        vcur = vnext; vnext = vpref;
    }

    // decision bits for the last column (t = T-1)
    {
        float sb = __shfl_up_sync(0xffffffffu, bt, 1);
        float bw;
        if (lane == 0) {
            if (w) {
                if (pc < T_ - 1) {
                    do { pc = ldsv1v(prog_src); } while (pc < T_ - 1);
                }
                uint2 s = ldsv2v(mb_src + (unsigned)(T_ - 1) * 8u);
                bw = __uint_as_float(s.y);
            } else bw = -PADM;
        } else bw = sb;
        unsigned bal = __ballot_sync(0xffffffffu, bw > bt);
        if (lane == 0) D[(T_ - 1) * 8 + w] = bal;
    }
    __syncthreads();

    // fixup: bit0 of warp0's word per column = (beta[255,c] > beta[0,c])
    {
        const float2* mbf = (const float2*)(smraw + SMB_MB);   // [8][1600]
        for (int c = l; c < T_; c += 256) {
            float b255 = mbf[7 * T_ + c].y;
            unsigned wv = D[c * 8];
            wv = (wv & ~1u) | ((b255 > b0h[c]) ? 1u : 0u);
            D[c * 8] = wv;
        }
    }
    __syncthreads();

    // serial backtrack with group-of-8 word prefetch
    if (l == 0) {
        int rows = tlm1;
        path[0] = rows;
        int k = 1;
        for (; k + 7 <= mlm1; k += 8) {
            int colbase = mlm1 - k;              // all >= 0
            int w0 = (rows & 255) >> 5;
            int w1 = (w0 + 7) & 7;
            unsigned Wa[8], Wb[8];
#pragma unroll
            for (int d2 = 0; d2 < 8; d2++) {
                Wa[d2] = D[(colbase - d2) * 8 + w0];
                Wb[d2] = D[(colbase - d2) * 8 + w1];
            }
#pragma unroll
            for (int d2 = 0; d2 < 8; d2++) {
                int br = rows & 255;
                unsigned word = ((br >> 5) == w0) ? Wa[d2] : Wb[d2];
                int is_go = (word >> (br & 31)) & 1;
                int tmp = rows - is_go + 1;
                rows = (tmp > 0 ? tmp : 0) - 1;
                path[k + d2] = rows;
            }
        }
        for (; k <= mlm1; k++) {
            int col = mlm1 - k;
            int br = rows & 255;
            unsigned word = D[col * 8 + (br >> 5)];
            int is_go = (word >> (br & 31)) & 1;
            int tmp = rows - is_go + 1;
            rows = (tmp > 0 ? tmp : 0) - 1;
            path[k] = rows;
        }
    }
    __syncthreads();

    // write one-hot ones: final[t] = onehot(path[ml-1-t]) for t < ml
    size_t abase = (size_t)b * T_ * L_;
    for (int t = l; t < ml; t += 256) {
        int r = path[mlm1 - t];
        if (r >= 0) out_align[abase + (size_t)t * L_ + r] = 1.0f;
    }
}

// ---------------- launch ----------------
extern "C" void kernel_launch(void* const* d_in, const int* in_sizes, int n_in,
                              void* d_out, int out_size) {
    const float* mu_logvar = (const float*)d_in[0];   // [B, L, 2C]
    const float* z         = (const float*)d_in[1];   // [B, C, T]
    const int*   tlen      = (const int*)d_in[2];     // [B]
    const int*   mlen      = (const int*)d_in[3];     // [B]

    float* out       = (float*)d_out;
    float* out_loss  = out;                                   // [B]
    float* out_align = out + B_;                              // [B, T, L]
    float* out_lp    = out_align + (size_t)B_ * T_ * L_;      // [B, L, T]

    cudaFuncSetAttribute(k2_dp, cudaFuncAttributeMaxDynamicSharedMemorySize,
                         SMB_TOT);

    kz_zero<<<2048, 256>>>((float4*)out_align, (B_ * T_ * L_) / 4);
    k0_coef<<<(B_ * L_) / 128, 128>>>(mu_logvar);
    dim3 g1(T_ / 64, L_ / 128, B_);
    k1_lp<<<g1, 256>>>(z, out_lp);
    k2_dp<<<B_, 256, SMB_TOT>>>(out_lp, tlen, mlen, out_loss, out_align);
}